// round 1
// baseline (speedup 1.0000x reference)
#include <cuda_runtime.h>

// Problem constants (from reference): N nodes, E edges, D=64 feature dim.
#define NN 50000
#define NE 800000
#define DD 64

// ---------------- device scratch (no allocations allowed) ----------------
__device__ float g_score[NE];     // per-edge attention logit
__device__ int   g_cnt[NN];       // dst histogram
__device__ int   g_cur[NN];       // scatter cursors
__device__ int   g_off[NN + 1];   // CSR offsets
__device__ int   g_eid[NE];       // CSR edge ids grouped by dst

// ---------------- helpers ----------------
__device__ __forceinline__ float warp_sum(float v) {
#pragma unroll
    for (int o = 16; o; o >>= 1) v += __shfl_xor_sync(0xffffffffu, v, o);
    return v;
}
__device__ __forceinline__ float warp_max(float v) {
#pragma unroll
    for (int o = 16; o; o >>= 1) v = fmaxf(v, __shfl_xor_sync(0xffffffffu, v, o));
    return v;
}

// ---------------- kernels ----------------
__global__ void zero_kernel() {
    int i = blockIdx.x * blockDim.x + threadIdx.x;
    if (i < NN) { g_cnt[i] = 0; g_cur[i] = 0; }
}

// One warp per edge: key = LN(relu(u*skw+skb + v*dkw+dkb)*ekw+ekb),
// score = dot(key, query[dst]). Also builds the dst histogram.
__global__ __launch_bounds__(256) void key_kernel(
    const float2* __restrict__ feat, const float2* __restrict__ query,
    const int* __restrict__ src, const int* __restrict__ dst,
    const float2* __restrict__ skw, const float2* __restrict__ skb,
    const float2* __restrict__ dkw, const float2* __restrict__ dkb,
    const float2* __restrict__ ekw, const float2* __restrict__ ekb,
    const float2* __restrict__ kgam, const float2* __restrict__ kbet)
{
    int warp = (blockIdx.x * blockDim.x + threadIdx.x) >> 5;
    int lane = threadIdx.x & 31;
    if (warp >= NE) return;
    const int e = warp;
    const int s = __ldg(src + e);
    const int d = __ldg(dst + e);

    float2 u  = __ldg(feat + s * 32 + lane);
    float2 v  = __ldg(feat + d * 32 + lane);
    float2 w1 = __ldg(skw + (size_t)e * 32 + lane);
    float2 b1 = __ldg(skb + (size_t)e * 32 + lane);
    float2 w2 = __ldg(dkw + (size_t)e * 32 + lane);
    float2 b2 = __ldg(dkb + (size_t)e * 32 + lane);
    float2 w3 = __ldg(ekw + (size_t)e * 32 + lane);
    float2 b3 = __ldg(ekb + (size_t)e * 32 + lane);

    float hx = fmaf(u.x, w1.x, b1.x) + fmaf(v.x, w2.x, b2.x);
    float hy = fmaf(u.y, w1.y, b1.y) + fmaf(v.y, w2.y, b2.y);
    hx = fmaxf(hx, 0.f); hy = fmaxf(hy, 0.f);
    hx = fmaf(hx, w3.x, b3.x); hy = fmaf(hy, w3.y, b3.y);

    float sum = warp_sum(hx + hy);
    float sq  = warp_sum(hx * hx + hy * hy);
    float mu  = sum * (1.f / 64.f);
    float var = sq * (1.f / 64.f) - mu * mu;
    float rs  = rsqrtf(var + 1e-5f);

    float2 g  = __ldg(kgam + lane);
    float2 be = __ldg(kbet + lane);
    float kx = fmaf((hx - mu) * rs, g.x, be.x);
    float ky = fmaf((hy - mu) * rs, g.y, be.y);

    float2 q = __ldg(query + d * 32 + lane);
    float dot = warp_sum(kx * q.x + ky * q.y);

    if (lane == 0) {
        g_score[e] = dot;
        atomicAdd(&g_cnt[d], 1);
    }
}

// Single-block exclusive scan over g_cnt -> g_off (N=50000, ~49 chunks of 1024).
__global__ void scan_kernel() {
    __shared__ int warp_sums[32];
    __shared__ int carry;
    int lane = threadIdx.x & 31, wid = threadIdx.x >> 5;
    if (threadIdx.x == 0) carry = 0;
    __syncthreads();
    for (int base = 0; base < NN; base += 1024) {
        int i = base + threadIdx.x;
        int x = (i < NN) ? g_cnt[i] : 0;
        int v = x;
#pragma unroll
        for (int o = 1; o < 32; o <<= 1) {
            int t = __shfl_up_sync(0xffffffffu, v, o);
            if (lane >= o) v += t;
        }
        if (lane == 31) warp_sums[wid] = v;
        __syncthreads();
        if (wid == 0) {
            int sv = warp_sums[lane];
#pragma unroll
            for (int o = 1; o < 32; o <<= 1) {
                int t = __shfl_up_sync(0xffffffffu, sv, o);
                if (lane >= o) sv += t;
            }
            warp_sums[lane] = sv;
        }
        __syncthreads();
        int incl = v + (wid > 0 ? warp_sums[wid - 1] : 0) + carry;
        if (i < NN) g_off[i] = incl - x;  // exclusive
        __syncthreads();
        if (threadIdx.x == 1023) carry = incl;
        __syncthreads();
    }
    if (threadIdx.x == 0) g_off[NN] = carry;
}

__global__ void scatter_kernel(const int* __restrict__ dst) {
    int e = blockIdx.x * blockDim.x + threadIdx.x;
    if (e >= NE) return;
    int d = __ldg(dst + e);
    int p = g_off[d] + atomicAdd(&g_cur[d], 1);
    g_eid[p] = e;
}

// One warp per node: segmented softmax over its CSR edges, value-FFN per edge,
// weighted accumulation, output LayerNorm — all fused, no scatter atomics.
__global__ __launch_bounds__(256) void out_kernel(
    const float2* __restrict__ feat, const int* __restrict__ src,
    const float2* __restrict__ svw, const float2* __restrict__ svb,
    const float2* __restrict__ dvw, const float2* __restrict__ dvb,
    const float2* __restrict__ evw, const float2* __restrict__ evb,
    const float2* __restrict__ vgam, const float2* __restrict__ vbet,
    const float2* __restrict__ agam, const float2* __restrict__ abet,
    float2* __restrict__ out, float* __restrict__ attn)
{
    int warp = (blockIdx.x * blockDim.x + threadIdx.x) >> 5;
    int lane = threadIdx.x & 31;
    if (warp >= NN) return;
    const int n = warp;
    const int beg = g_off[n], end = g_off[n + 1];

    // segment max
    float m = -3.0e38f;
    for (int i = beg + lane; i < end; i += 32) m = fmaxf(m, g_score[g_eid[i]]);
    m = warp_max(m);

    float2 v   = __ldg(feat + n * 32 + lane);
    float2 vg  = __ldg(vgam + lane);
    float2 vb  = __ldg(vbet + lane);

    float accx = 0.f, accy = 0.f, sumex = 0.f;
    for (int i = beg; i < end; i++) {
        int e = g_eid[i];                         // warp-uniform broadcast
        float ex = __expf(g_score[e] - m);
        sumex += ex;
        int s = __ldg(src + e);
        float2 u  = __ldg(feat + s * 32 + lane);
        float2 w1 = __ldg(svw + (size_t)e * 32 + lane);
        float2 b1 = __ldg(svb + (size_t)e * 32 + lane);
        float2 w2 = __ldg(dvw + (size_t)e * 32 + lane);
        float2 b2 = __ldg(dvb + (size_t)e * 32 + lane);
        float2 w3 = __ldg(evw + (size_t)e * 32 + lane);
        float2 b3 = __ldg(evb + (size_t)e * 32 + lane);

        float hx = fmaf(u.x, w1.x, b1.x) + fmaf(v.x, w2.x, b2.x);
        float hy = fmaf(u.y, w1.y, b1.y) + fmaf(v.y, w2.y, b2.y);
        hx = fmaxf(hx, 0.f); hy = fmaxf(hy, 0.f);
        hx = fmaf(hx, w3.x, b3.x); hy = fmaf(hy, w3.y, b3.y);

        float sum = warp_sum(hx + hy);
        float sq  = warp_sum(hx * hx + hy * hy);
        float mu  = sum * (1.f / 64.f);
        float var = sq * (1.f / 64.f) - mu * mu;
        float rs  = rsqrtf(var + 1e-5f);
        float vx = fmaf((hx - mu) * rs, vg.x, vb.x);
        float vy = fmaf((hy - mu) * rs, vg.y, vb.y);
        accx = fmaf(vx, ex, accx);
        accy = fmaf(vy, ex, accy);
    }
    float inv = (sumex > 0.f) ? __frcp_rn(sumex) : 0.f;

    // attn output (each edge appears exactly once in CSR)
    for (int i = beg + lane; i < end; i += 32) {
        int e = g_eid[i];
        attn[e] = __expf(g_score[e] - m) * inv;
    }

    // normalize + output LayerNorm (empty segment -> zeros -> LN gives beta, matches ref)
    float ox = accx * inv, oy = accy * inv;
    float sum = warp_sum(ox + oy);
    float sq  = warp_sum(ox * ox + oy * oy);
    float mu  = sum * (1.f / 64.f);
    float var = sq * (1.f / 64.f) - mu * mu;
    float rs  = rsqrtf(var + 1e-5f);
    float2 ag = __ldg(agam + lane);
    float2 ab = __ldg(abet + lane);
    float2 o2;
    o2.x = fmaf((ox - mu) * rs, ag.x, ab.x);
    o2.y = fmaf((oy - mu) * rs, ag.y, ab.y);
    out[(size_t)n * 32 + lane] = o2;
}

// ---------------- launch ----------------
extern "C" void kernel_launch(void* const* d_in, const int* in_sizes, int n_in,
                              void* d_out, int out_size)
{
    // metadata order == setup_inputs dict order
    const float2* feat  = (const float2*)d_in[0];
    const float2* query = (const float2*)d_in[1];
    const int*    src   = (const int*)d_in[2];
    const int*    dst   = (const int*)d_in[3];
    const float2* skw = (const float2*)d_in[4];
    const float2* skb = (const float2*)d_in[5];
    const float2* dkw = (const float2*)d_in[6];
    const float2* dkb = (const float2*)d_in[7];
    const float2* ekw = (const float2*)d_in[8];
    const float2* ekb = (const float2*)d_in[9];
    const float2* svw = (const float2*)d_in[10];
    const float2* svb = (const float2*)d_in[11];
    const float2* dvw = (const float2*)d_in[12];
    const float2* dvb = (const float2*)d_in[13];
    const float2* evw = (const float2*)d_in[14];
    const float2* evb = (const float2*)d_in[15];
    const float2* kgam = (const float2*)d_in[16];
    const float2* kbet = (const float2*)d_in[17];
    const float2* vgam = (const float2*)d_in[18];
    const float2* vbet = (const float2*)d_in[19];
    const float2* agam = (const float2*)d_in[20];
    const float2* abet = (const float2*)d_in[21];

    float* out_f = (float*)d_out;                 // [N, D] first
    float* attn  = out_f + (size_t)NN * DD;       // then [E, 1]

    zero_kernel<<<(NN + 255) / 256, 256>>>();
    key_kernel<<<(NE * 32 + 255) / 256, 256>>>(feat, query, src, dst,
                                               skw, skb, dkw, dkb, ekw, ekb,
                                               kgam, kbet);
    scan_kernel<<<1, 1024>>>();
    scatter_kernel<<<(NE + 255) / 256, 256>>>(dst);
    out_kernel<<<(NN * 32 + 255) / 256, 256>>>(feat, src,
                                               svw, svb, dvw, dvb, evw, evb,
                                               vgam, vbet, agam, abet,
                                               (float2*)out_f, attn);
}